// round 9
// baseline (speedup 1.0000x reference)
#include <cuda_runtime.h>
#include <cstdint>

// PushingEnv: B independent 2-body contact sims, H=200 Euler steps.
//
// Algebraic restructuring (C=1, DT=0.01, K=100, K*DT = 1 exactly):
//   sum coords  s = x1+x2, sv = v1+v2: contact force cancels ->
//       closed form s_H = s0 + C_SUM*sv0   (C_SUM = sum 0.01*0.99^n)
//   diff coords w = x1-x2:
//       a := -0.02*(w+1), q := 0.01*(v1-v2)
//       per step: r = min(a,0); q = 0.99*q + r; a = a - 0.02*q
//   recover w = -50*a - 1; x1=(s+w)/2; x2=(s-w)/2; loss=(x2-goal)^2.
//
// R9: whole mainloop as ONE asm block of straight-line f32x2 PTX so the
// pair split/join movs are block-local and coalescable by ptxas (the
// per-step asm blocks of R4/R7/R8 pinned operands to the asm interface
// every step, leaving ~5-6 instr/step; target here is 4: 2xFMNMX+2xFFMA2
// per 2 envs). Geometry = R3's measured best: 128 thr x 1024 CTAs.

constexpr int H = 200;

constexpr float compute_c_sum() {
    float sv = 1.0f, s = 0.0f;
    for (int i = 0; i < H; ++i) { sv *= 0.99f; s += 0.01f * sv; }
    return s;
}
constexpr float C_SUM = compute_c_sum();

__device__ __forceinline__ uint64_t pack2(float lo, float hi) {
    uint64_t d;
    asm("mov.b64 %0, {%1, %2};" : "=l"(d) : "f"(lo), "f"(hi));
    return d;
}
__device__ __forceinline__ void unpack2(uint64_t d, float& lo, float& hi) {
    asm("mov.b64 {%0, %1}, %2;" : "=f"(lo), "=f"(hi) : "l"(d));
}

// One step of the packed recurrence as raw PTX text (operands are asm-local
// .reg names, NOT interface operands -> ptxas can coalesce the pair movs).
#define STEP_TXT                                        \
    "mov.b64 {al, ah}, vA;\n\t"                         \
    "min.f32 rl, al, 0f00000000;\n\t"                   \
    "min.f32 rh, ah, 0f00000000;\n\t"                   \
    "mov.b64 vR, {rl, rh};\n\t"                         \
    "fma.rn.f32x2 vQ, vQ, vC, vR;\n\t"                  \
    "fma.rn.f32x2 vA, vQ, vD, vA;\n\t"

#define STEP_X8 STEP_TXT STEP_TXT STEP_TXT STEP_TXT STEP_TXT STEP_TXT STEP_TXT STEP_TXT
#define STEP_X40 STEP_X8 STEP_X8 STEP_X8 STEP_X8 STEP_X8
#define STEP_X200 STEP_X40 STEP_X40 STEP_X40 STEP_X40 STEP_X40

__global__ void __launch_bounds__(128) pushing_env_kernel(
    const float* __restrict__ x1_0,
    const float* __restrict__ v1_0,
    const float* __restrict__ x2_0,
    const float* __restrict__ v2_0,
    const float* __restrict__ goal,
    float* __restrict__ out,
    int n)
{
    int i = blockIdx.x * blockDim.x + threadIdx.x;  // pair index
    int j = 2 * i;
    if (j >= n) return;

    if (j + 1 < n) {
        float2 X1 = *(const float2*)(x1_0 + j);
        float2 V1 = *(const float2*)(v1_0 + j);
        float2 X2 = *(const float2*)(x2_0 + j);
        float2 V2 = *(const float2*)(v2_0 + j);
        float2 G  = *(const float2*)(goal + j);

        // packed difference-mode chain (2 envs)
        uint64_t Q = pack2(0.01f * (V1.x - V2.x), 0.01f * (V1.y - V2.y));
        uint64_t A = pack2(fmaf(X1.x - X2.x, -0.02f, -0.02f),
                           fmaf(X1.y - X2.y, -0.02f, -0.02f));
        const uint64_t C99  = pack2(0.99f, 0.99f);
        const uint64_t CM02 = pack2(-0.02f, -0.02f);

        // entire 200-step loop: one straight-line asm block
        asm("{\n\t"
            ".reg .f32 al, ah, rl, rh;\n\t"
            ".reg .b64 vQ, vA, vR, vC, vD;\n\t"
            "mov.b64 vQ, %0;\n\t"
            "mov.b64 vA, %1;\n\t"
            "mov.b64 vC, %2;\n\t"
            "mov.b64 vD, %3;\n\t"
            STEP_X200
            "mov.b64 %0, vQ;\n\t"
            "mov.b64 %1, vA;\n\t"
            "}"
            : "+l"(Q), "+l"(A) : "l"(C99), "l"(CM02));

        float a0, a1;
        unpack2(A, a0, a1);
        float w0 = fmaf(a0, -50.0f, -1.0f);
        float w1 = fmaf(a1, -50.0f, -1.0f);

        // sum-mode closed form
        float s0 = fmaf(V1.x + V2.x, C_SUM, X1.x + X2.x);
        float s1 = fmaf(V1.y + V2.y, C_SUM, X1.y + X2.y);

        float2 xf1 = make_float2(0.5f * (s0 + w0), 0.5f * (s1 + w1));
        float2 xf2 = make_float2(0.5f * (s0 - w0), 0.5f * (s1 - w1));
        float d0 = xf2.x - G.x;
        float d1 = xf2.y - G.y;

        *(float2*)(out + j)         = make_float2(d0 * d0, d1 * d1);
        *(float2*)(out + n + j)     = xf1;
        *(float2*)(out + 2 * n + j) = xf2;
    } else {
        // scalar tail (n odd; not hit for B=262144)
        float x1 = x1_0[j], v1 = v1_0[j], x2 = x2_0[j], v2 = v2_0[j];
        float q = 0.01f * (v1 - v2);
        float a = fmaf(x1 - x2, -0.02f, -0.02f);
        #pragma unroll
        for (int t = 0; t < H; ++t) {
            float r = fminf(a, 0.0f);
            q = fmaf(q, 0.99f, r);
            a = fmaf(q, -0.02f, a);
        }
        float w = fmaf(a, -50.0f, -1.0f);
        float s = fmaf(v1 + v2, C_SUM, x1 + x2);
        float xf1 = 0.5f * (s + w);
        float xf2 = 0.5f * (s - w);
        float d = xf2 - goal[j];
        out[j] = d * d;
        out[n + j] = xf1;
        out[2 * n + j] = xf2;
    }
}

extern "C" void kernel_launch(void* const* d_in, const int* in_sizes, int n_in,
                              void* d_out, int out_size)
{
    // inputs: [0]=u_seq(H) [1]=x1_0 [2]=v1_0 [3]=x2_0 [4]=v2_0 [5]=goal [6]=gtype
    const float* x1_0 = (const float*)d_in[1];
    const float* v1_0 = (const float*)d_in[2];
    const float* x2_0 = (const float*)d_in[3];
    const float* v2_0 = (const float*)d_in[4];
    const float* goal = (const float*)d_in[5];
    int n = in_sizes[1];

    int threads = 128;
    int pairs = (n + 1) / 2;
    int blocks = (pairs + threads - 1) / threads;
    pushing_env_kernel<<<blocks, threads>>>(x1_0, v1_0, x2_0, v2_0, goal,
                                            (float*)d_out, n);
}

// round 10
// speedup vs baseline: 1.1146x; 1.1146x over previous
#include <cuda_runtime.h>

// PushingEnv: B independent 2-body contact sims, H=200 Euler steps.
//
// Exact transform (C=1, DT=0.01, K=100, K*DT=1):
//   sum coords: closed form s_H = s0 + C_SUM*(v1+v2)   (force cancels)
//   diff coords: a = -0.02*(w+1), q = 0.01*(v1-v2)
//     step: r = min(a,0); q = 0.99q + r; a = a - 0.02q
//   recover w = -50a - 1; x1=(s+w)/2; x2=(s-w)/2; loss=(x2-goal)^2.
//
// R10: contact-free envs (~92% of this distribution) have LINEAR diff
// dynamics with a closed form: q_t = 0.99^t q0, a_t = a0 - 0.02*q0*S_t,
// and a_t is MONOTONE in t, so "never in contact" <=> both endpoint
// checks a_0 >= delta and a_199 >= delta. Those envs skip the loop
// entirely. Contact/borderline envs are compacted into shared memory per
// 512-env block and iterated exactly by <=2 warps, using a re-associated
// 4-instr step whose serial chain is ~10 cyc instead of ~14.
// (fma.rn.f32x2 abandoned for good: sm_100a has no FFMA2 — back-solved
// instruction counts across R3-R9 show ptxas lowers it to 2xFFMA + movs.)

constexpr int H = 200;
constexpr int THREADS = 256;
constexpr int ENVS_PER_BLOCK = 2 * THREADS;   // 512

constexpr float compute_c_sum() {           // 0.01 * sum_{i=1..H} 0.99^i
    float sv = 1.0f, s = 0.0f;
    for (int i = 0; i < H; ++i) { sv *= 0.99f; s += 0.01f * sv; }
    return s;
}
constexpr float C_SUM = compute_c_sum();

constexpr float compute_S(int t) {          // sum_{i=1..t} 0.99^i
    float p = 1.0f, s = 0.0f;
    for (int i = 0; i < t; ++i) { p *= 0.99f; s += p; }
    return s;
}
constexpr float COEF_PRED = 0.02f * compute_S(H - 1);  // for a_{H-1}
constexpr float COEF_AH   = 0.02f * compute_S(H);      // for a_H
constexpr float DELTA = 1e-5f;

__global__ void __launch_bounds__(THREADS) pushing_env_kernel(
    const float* __restrict__ x1_0,
    const float* __restrict__ v1_0,
    const float* __restrict__ x2_0,
    const float* __restrict__ v2_0,
    const float* __restrict__ goal,
    float* __restrict__ out,
    int n)
{
    __shared__ float sq[ENVS_PER_BLOCK];
    __shared__ float sa[ENVS_PER_BLOCK];
    __shared__ float ss[ENVS_PER_BLOCK];
    __shared__ float sg[ENVS_PER_BLOCK];
    __shared__ int   sj[ENVS_PER_BLOCK];
    __shared__ int   cnt;

    const int tid = threadIdx.x;
    if (tid == 0) cnt = 0;
    __syncthreads();

    const int j = blockIdx.x * ENVS_PER_BLOCK + 2 * tid;

    // ---- phase 1: predicate + closed form for contact-free envs ----
    #pragma unroll
    for (int e = 0; e < 2; ++e) {
        int k = j + e;
        if (k < n) {
            float x1 = x1_0[k], v1 = v1_0[k];
            float x2 = x2_0[k], v2 = v2_0[k];
            float g  = goal[k];

            float q0 = 0.01f * (v1 - v2);
            float a0 = fmaf(x1 - x2, -0.02f, -0.02f);   // -0.02*(w0+1)
            float s  = fmaf(v1 + v2, C_SUM, x1 + x2);   // s_H closed form

            // a_t monotone: endpoints suffice. a_{H-1} = a0 - COEF_PRED*q0.
            float a_end = fmaf(q0, -COEF_PRED, a0);
            if (a0 >= DELTA && a_end >= DELTA) {
                // never in contact: a_H = a0 - COEF_AH*q0
                float aH = fmaf(q0, -COEF_AH, a0);
                float w  = fmaf(aH, -50.0f, -1.0f);
                float xf1 = 0.5f * (s + w);
                float xf2 = 0.5f * (s - w);
                float d = xf2 - g;
                out[k]         = d * d;
                out[n + k]     = xf1;
                out[2 * n + k] = xf2;
            } else {
                int p = atomicAdd(&cnt, 1);
                sq[p] = q0; sa[p] = a0; ss[p] = s; sg[p] = g; sj[p] = k;
            }
        }
    }
    __syncthreads();

    // ---- phase 2: exact iteration for compacted contact envs ----
    const int c = cnt;
    for (int k = tid; k < c; k += THREADS) {
        float q = sq[k];
        float a = sa[k];
        // re-associated step: a_t = a - 0.0198*q - 0.02*r keeps the
        // q-FMA off the min->a critical path (chain ~10 cyc/step).
        #pragma unroll
        for (int t = 0; t < H; ++t) {
            float inner = fmaf(q, -0.0198f, a);   // a - 0.02*0.99*q_old
            float r = fminf(a, 0.0f);
            q = fmaf(q, 0.99f, r);                // q_new = 0.99q + r
            a = fmaf(r, -0.02f, inner);           // a_new
        }
        float s = ss[k];
        float w = fmaf(a, -50.0f, -1.0f);
        float xf1 = 0.5f * (s + w);
        float xf2 = 0.5f * (s - w);
        float d = xf2 - sg[k];
        int o = sj[k];
        out[o]         = d * d;
        out[n + o]     = xf1;
        out[2 * n + o] = xf2;
    }
}

extern "C" void kernel_launch(void* const* d_in, const int* in_sizes, int n_in,
                              void* d_out, int out_size)
{
    // inputs: [0]=u_seq(H) [1]=x1_0 [2]=v1_0 [3]=x2_0 [4]=v2_0 [5]=goal [6]=gtype
    const float* x1_0 = (const float*)d_in[1];
    const float* v1_0 = (const float*)d_in[2];
    const float* x2_0 = (const float*)d_in[3];
    const float* v2_0 = (const float*)d_in[4];
    const float* goal = (const float*)d_in[5];
    int n = in_sizes[1];

    int blocks = (n + ENVS_PER_BLOCK - 1) / ENVS_PER_BLOCK;
    pushing_env_kernel<<<blocks, THREADS>>>(x1_0, v1_0, x2_0, v2_0, goal,
                                            (float*)d_out, n);
}

// round 11
// speedup vs baseline: 1.2490x; 1.1206x over previous
#include <cuda_runtime.h>

// PushingEnv: B independent 2-body contact sims, H=200 Euler steps.
//
// Exact transform (C=1, DT=0.01, K=100, K*DT=1):
//   sum coords: closed form s_H = s0 + C_SUM*(v1+v2)      (force cancels)
//   diff coords: a = -0.02*(w+1), q = 0.01*(v1-v2)
//     step: r = min(a,0); q = 0.99q + r; a = a - 0.02q
//   recover w = -50a - 1; x1=(s+w)/2; x2=(s-w)/2; loss=(x2-goal)^2.
//
// R11: single-contact-episode theorem. Out of contact a is monotone
// (increment -0.0198q, q sign-fixed, geometric decay); entry needs q>0;
// the spring reverses relative velocity so at exit (a>=0) q<=0, after
// which a is monotone increasing -> at most ONE episode (~25 steps,
// half-period of the contact oscillator). So per contact env:
//   1) closed-form jump to entry step t1 (one __log2f + exp2f),
//   2) exact-iterate only the episode, exit on invariant a>=0 && q<=0,
//   3) closed-form linear tail (one exp2f).
// Boundary off-by-one injects only O(delta) into q -> ~1e-6 rel, same
// robustness argument the R10 predicate validated empirically.

constexpr int H = 200;
constexpr int THREADS = 256;
constexpr int ENVS_PER_BLOCK = 2 * THREADS;   // 512

constexpr float compute_c_sum() {             // 0.01 * sum_{i=1..H} 0.99^i
    float sv = 1.0f, s = 0.0f;
    for (int i = 0; i < H; ++i) { sv *= 0.99f; s += 0.01f * sv; }
    return s;
}
constexpr float C_SUM = compute_c_sum();

constexpr float compute_S(int t) {            // sum_{i=1..t} 0.99^i
    float p = 1.0f, s = 0.0f;
    for (int i = 0; i < t; ++i) { p *= 0.99f; s += p; }
    return s;
}
constexpr float COEF_PRED = 0.02f * compute_S(H - 1);  // a_{H-1} coefficient
constexpr float COEF_AH   = 0.02f * compute_S(H);      // a_H coefficient
constexpr float DELTA = 1e-5f;

// log2(0.99) and its reciprocal (double-precision constants rounded to f32;
// the -2 step slack absorbs all MUFU/rounding error in the jump).
constexpr float LOG2_099     = -0.014499569695115089f;
constexpr float INV_LOG2_099 = -68.967560f;

__global__ void __launch_bounds__(THREADS) pushing_env_kernel(
    const float* __restrict__ x1_0,
    const float* __restrict__ v1_0,
    const float* __restrict__ x2_0,
    const float* __restrict__ v2_0,
    const float* __restrict__ goal,
    float* __restrict__ out,
    int n)
{
    __shared__ float sq[ENVS_PER_BLOCK];
    __shared__ float sa[ENVS_PER_BLOCK];
    __shared__ float ss[ENVS_PER_BLOCK];
    __shared__ float sg[ENVS_PER_BLOCK];
    __shared__ int   sj[ENVS_PER_BLOCK];
    __shared__ int   cnt;

    const int tid = threadIdx.x;
    if (tid == 0) cnt = 0;
    __syncthreads();

    const int j = blockIdx.x * ENVS_PER_BLOCK + 2 * tid;

    // ---- phase 1: predicate + closed form for contact-free envs ----
    float q0[2], a0[2], sC[2], gC[2];
    bool  need[2] = {false, false};
    if (j + 1 < n) {
        float2 X1 = *(const float2*)(x1_0 + j);
        float2 V1 = *(const float2*)(v1_0 + j);
        float2 X2 = *(const float2*)(x2_0 + j);
        float2 V2 = *(const float2*)(v2_0 + j);
        float2 G  = *(const float2*)(goal + j);
        q0[0] = 0.01f * (V1.x - V2.x);
        q0[1] = 0.01f * (V1.y - V2.y);
        a0[0] = fmaf(X1.x - X2.x, -0.02f, -0.02f);
        a0[1] = fmaf(X1.y - X2.y, -0.02f, -0.02f);
        sC[0] = fmaf(V1.x + V2.x, C_SUM, X1.x + X2.x);
        sC[1] = fmaf(V1.y + V2.y, C_SUM, X1.y + X2.y);
        gC[0] = G.x; gC[1] = G.y;
        need[0] = need[1] = true;
    } else {
        for (int e = 0; e < 2; ++e) {
            int k = j + e;
            if (k < n) {
                float x1 = x1_0[k], v1 = v1_0[k], x2 = x2_0[k], v2 = v2_0[k];
                q0[e] = 0.01f * (v1 - v2);
                a0[e] = fmaf(x1 - x2, -0.02f, -0.02f);
                sC[e] = fmaf(v1 + v2, C_SUM, x1 + x2);
                gC[e] = goal[k];
                need[e] = true;
            }
        }
    }

    #pragma unroll
    for (int e = 0; e < 2; ++e) {
        if (need[e]) {
            int k = j + e;
            // a_t monotone while linear: endpoints suffice.
            float a_end = fmaf(q0[e], -COEF_PRED, a0[e]);
            if (a0[e] >= DELTA && a_end >= DELTA) {
                float aH = fmaf(q0[e], -COEF_AH, a0[e]);
                float w  = fmaf(aH, -50.0f, -1.0f);
                float xf1 = 0.5f * (sC[e] + w);
                float xf2 = 0.5f * (sC[e] - w);
                float d = xf2 - gC[e];
                out[k]         = d * d;
                out[n + k]     = xf1;
                out[2 * n + k] = xf2;
            } else {
                int p = atomicAdd(&cnt, 1);
                sq[p] = q0[e]; sa[p] = a0[e]; ss[p] = sC[e];
                sg[p] = gC[e]; sj[p] = k;
            }
        }
    }
    __syncthreads();

    // ---- phase 2: episode-clipped exact iteration for contact envs ----
    const int c = cnt;
    for (int k = tid; k < c; k += THREADS) {
        float q = sq[k];
        float a = sa[k];
        int   t = 0;

        if (a >= DELTA) {
            // delayed contact: q > 0 guaranteed (else a_end >= a0 >= DELTA).
            // Solve a0 - 0.02*q0*S_t = DELTA for t; S_t = 99*(1 - 0.99^t).
            float Sstar = (a - DELTA) * (50.0f / q);
            float arg   = fmaf(Sstar, -(1.0f / 99.0f), 1.0f);  // in (0.13, 1]
            float t1f   = __log2f(arg) * INV_LOG2_099;
            t = (int)t1f - 2;                    // slack for MUFU error
            if (t < 0) t = 0;
            if (t > H) t = H;
            float p = exp2f((float)t * LOG2_099);        // 0.99^t
            a = fmaf(-1.98f * q, 1.0f - p, a);           // a0 - 0.02*q0*S_t
            q = q * p;                                   // q0 * 0.99^t
        }

        // exact episode loop; exit invariant: a>=0 && q<=0 => linear &
        // monotone increasing forever (no re-entry possible).
        while (t < H) {
            if (a >= 0.0f && q <= 0.0f) break;
            float inner = fmaf(q, -0.0198f, a);   // a - 0.02*0.99*q_old
            float r = fminf(a, 0.0f);
            q = fmaf(q, 0.99f, r);
            a = fmaf(r, -0.02f, inner);
            ++t;
        }

        // closed-form linear tail over remaining H-t steps (no-op if t==H).
        float p2 = exp2f((float)(H - t) * LOG2_099);
        a = fmaf(-1.98f * q, 1.0f - p2, a);

        float s = ss[k];
        float w = fmaf(a, -50.0f, -1.0f);
        float xf1 = 0.5f * (s + w);
        float xf2 = 0.5f * (s - w);
        float d = xf2 - sg[k];
        int o = sj[k];
        out[o]         = d * d;
        out[n + o]     = xf1;
        out[2 * n + o] = xf2;
    }
}

extern "C" void kernel_launch(void* const* d_in, const int* in_sizes, int n_in,
                              void* d_out, int out_size)
{
    // inputs: [0]=u_seq(H) [1]=x1_0 [2]=v1_0 [3]=x2_0 [4]=v2_0 [5]=goal [6]=gtype
    const float* x1_0 = (const float*)d_in[1];
    const float* v1_0 = (const float*)d_in[2];
    const float* x2_0 = (const float*)d_in[3];
    const float* v2_0 = (const float*)d_in[4];
    const float* goal = (const float*)d_in[5];
    int n = in_sizes[1];

    int blocks = (n + ENVS_PER_BLOCK - 1) / ENVS_PER_BLOCK;
    pushing_env_kernel<<<blocks, THREADS>>>(x1_0, v1_0, x2_0, v2_0, goal,
                                            (float*)d_out, n);
}